// round 1
// baseline (speedup 1.0000x reference)
#include <cuda_runtime.h>
#include <math.h>

#define S_LEN 2048
#define EMB   1024
#define NH    16
#define HD    64
#define BATCH 2
#define M_TOK (BATCH * S_LEN)   // 4096

// Scratch (device globals: no allocation allowed in kernel_launch)
__device__ float g_q[BATCH * NH * S_LEN * HD];   // [B,H,S,D]
__device__ float g_k[BATCH * NH * S_LEN * HD];
__device__ float g_v[BATCH * NH * S_LEN * HD];
__device__ float g_att[M_TOK * EMB];             // [B,S,E]

// ---------------------------------------------------------------------------
// C = A[M,K] @ W[N,K]^T   (torch Linear convention)
// mode 0: C row-major [M,N]
// mode 1: scatter to [B,H,S,D] layout (QKV projections)
// ---------------------------------------------------------------------------
__global__ __launch_bounds__(256) void sgemm_nt(const float* __restrict__ A,
                                                const float* __restrict__ W,
                                                float* __restrict__ C,
                                                int M, int N, int K, int mode)
{
    __shared__ float As[8][128];
    __shared__ float Bs[8][128];

    const int tid = threadIdx.x;
    const int bn0 = blockIdx.x * 128;
    const int bm0 = blockIdx.y * 128;
    const int tx = tid & 15;        // n direction, 8 cols each
    const int ty = tid >> 4;        // m direction, 8 rows each
    const int lrow = tid >> 1;      // 0..127
    const int lkp  = (tid & 1) * 4; // 0 or 4

    float acc[8][8];
#pragma unroll
    for (int i = 0; i < 8; i++)
#pragma unroll
        for (int j = 0; j < 8; j++) acc[i][j] = 0.0f;

    const float* Aload = A + (size_t)(bm0 + lrow) * K + lkp;
    const float* Bload = W + (size_t)(bn0 + lrow) * K + lkp;

    for (int k0 = 0; k0 < K; k0 += 8) {
        float4 av = *(const float4*)(Aload + k0);
        float4 bv = *(const float4*)(Bload + k0);
        As[lkp + 0][lrow] = av.x; As[lkp + 1][lrow] = av.y;
        As[lkp + 2][lrow] = av.z; As[lkp + 3][lrow] = av.w;
        Bs[lkp + 0][lrow] = bv.x; Bs[lkp + 1][lrow] = bv.y;
        Bs[lkp + 2][lrow] = bv.z; Bs[lkp + 3][lrow] = bv.w;
        __syncthreads();

#pragma unroll
        for (int kk = 0; kk < 8; kk++) {
            float4 a0 = *(const float4*)&As[kk][ty * 8];
            float4 a1 = *(const float4*)&As[kk][ty * 8 + 4];
            float4 b0 = *(const float4*)&Bs[kk][tx * 8];
            float4 b1 = *(const float4*)&Bs[kk][tx * 8 + 4];
            float ar[8] = {a0.x, a0.y, a0.z, a0.w, a1.x, a1.y, a1.z, a1.w};
            float br[8] = {b0.x, b0.y, b0.z, b0.w, b1.x, b1.y, b1.z, b1.w};
#pragma unroll
            for (int i = 0; i < 8; i++)
#pragma unroll
                for (int j = 0; j < 8; j++)
                    acc[i][j] = fmaf(ar[i], br[j], acc[i][j]);
        }
        __syncthreads();
    }

    if (mode == 0) {
#pragma unroll
        for (int i = 0; i < 8; i++) {
            size_t row = (size_t)(bm0 + ty * 8 + i) * N + bn0 + tx * 8;
            *(float4*)&C[row]     = make_float4(acc[i][0], acc[i][1], acc[i][2], acc[i][3]);
            *(float4*)&C[row + 4] = make_float4(acc[i][4], acc[i][5], acc[i][6], acc[i][7]);
        }
    } else {
#pragma unroll
        for (int i = 0; i < 8; i++) {
            int m = bm0 + ty * 8 + i;
            int b = m >> 11;          // / S_LEN
            int s = m & (S_LEN - 1);
#pragma unroll
            for (int jv = 0; jv < 8; jv += 4) {
                int f = bn0 + tx * 8 + jv;
                int h = f >> 6;       // / HD
                int d = f & (HD - 1);
                size_t dst = (((size_t)(b * NH + h) * S_LEN + s) * HD) + d;
                *(float4*)&C[dst] = make_float4(acc[i][jv], acc[i][jv + 1],
                                                acc[i][jv + 2], acc[i][jv + 3]);
            }
        }
    }
}

// ---------------------------------------------------------------------------
// RoPE in-place on q,k ([B,H,S,D]); pair (d, d+32), same theta for both halves.
// ---------------------------------------------------------------------------
__global__ __launch_bounds__(256) void rope_kernel(float* __restrict__ q,
                                                   float* __restrict__ k)
{
    int t = blockIdx.x * blockDim.x + threadIdx.x;   // over B*H*S*32
    int i  = t & 31;
    int s  = (t >> 5) & (S_LEN - 1);
    int bh = t >> 16;                                // / (S_LEN*32)
    float inv_freq = powf(10000.0f, -(float)i * (1.0f / 32.0f));
    float theta = (float)s * inv_freq;
    float sn, cs;
    sincosf(theta, &sn, &cs);
    size_t base = ((size_t)bh * S_LEN + s) * HD;
    float q1 = q[base + i], q2 = q[base + i + 32];
    q[base + i]      = q1 * cs - q2 * sn;
    q[base + i + 32] = q2 * cs + q1 * sn;
    float k1 = k[base + i], k2 = k[base + i + 32];
    k[base + i]      = k1 * cs - k2 * sn;
    k[base + i + 32] = k2 * cs + k1 * sn;
}

// ---------------------------------------------------------------------------
// Causal flash attention, 64x64 tiles, 256 threads (16x16), fp32.
// Q/K stored d-major in smem with XOR swizzle (conflict-free float4 reads).
// Output written in [B,S,H,D] (= [B,S,E]) layout.
// ---------------------------------------------------------------------------
#define NEG_INF (-1e30f)

__device__ __forceinline__ int sw_idx(int d, int j) {
    // float offset of logical element (d-row, j-col) in a 64x64 tile
    return (d * 16 + ((j >> 2) ^ (d & 15))) * 4 + (j & 3);
}

__global__ __launch_bounds__(256) void flash_kernel(const float* __restrict__ Q,
                                                    const float* __restrict__ K,
                                                    const float* __restrict__ V,
                                                    float* __restrict__ O)
{
    extern __shared__ float sm[];
    float* q_s = sm;            // 4096 floats, swizzled, [d][r]
    float* k_s = sm + 4096;     // swizzled, [d][j]
    float* v_s = sm + 8192;     // [j][d] plain 64x64
    float* p_s = sm + 12288;    // [r][j] plain 64x64

    const int qt = blockIdx.x;
    const int bh = blockIdx.y;
    const int tid = threadIdx.x;
    const int tx = tid & 15;    // k-col / d-col group (4 each)
    const int ty = tid >> 4;    // q-row group (4 each)

    const float* Qb = Q + ((size_t)bh * S_LEN + qt * 64) * HD;
    const float* Kb = K + (size_t)bh * S_LEN * HD;
    const float* Vb = V + (size_t)bh * S_LEN * HD;

    // Load Q tile (transposed+swizzled), pre-scaled by 1/sqrt(D)
    for (int idx = tid; idx < 4096; idx += 256) {
        int r = idx >> 6, d = idx & 63;
        q_s[sw_idx(d, r)] = Qb[idx] * 0.125f;
    }
    __syncthreads();

    float m_i[4], l_i[4], o[4][4];
#pragma unroll
    for (int i = 0; i < 4; i++) {
        m_i[i] = NEG_INF; l_i[i] = 0.0f;
#pragma unroll
        for (int c = 0; c < 4; c++) o[i][c] = 0.0f;
    }

    for (int kt = 0; kt <= qt; kt++) {
        __syncthreads();   // protect k_s/v_s from previous iteration readers
        for (int idx = tid; idx < 4096; idx += 256) {
            int j = idx >> 6, d = idx & 63;
            size_t g = (size_t)(kt * 64 + j) * HD + d;
            k_s[sw_idx(d, j)] = Kb[g];
            v_s[j * 64 + d]   = Vb[g];
        }
        __syncthreads();

        float s[4][4];
#pragma unroll
        for (int i = 0; i < 4; i++)
#pragma unroll
            for (int c = 0; c < 4; c++) s[i][c] = 0.0f;

#pragma unroll 8
        for (int d = 0; d < 64; d++) {
            float4 qa = *(const float4*)&q_s[(d * 16 + (ty ^ (d & 15))) * 4];
            float4 kb = *(const float4*)&k_s[(d * 16 + (tx ^ (d & 15))) * 4];
            float ar[4] = {qa.x, qa.y, qa.z, qa.w};
            float br[4] = {kb.x, kb.y, kb.z, kb.w};
#pragma unroll
            for (int i = 0; i < 4; i++)
#pragma unroll
                for (int c = 0; c < 4; c++)
                    s[i][c] = fmaf(ar[i], br[c], s[i][c]);
        }

        if (kt == qt) {
#pragma unroll
            for (int i = 0; i < 4; i++)
#pragma unroll
                for (int c = 0; c < 4; c++)
                    if (4 * tx + c > 4 * ty + i) s[i][c] = NEG_INF;
        }

#pragma unroll
        for (int i = 0; i < 4; i++) {
            float rm = fmaxf(fmaxf(s[i][0], s[i][1]), fmaxf(s[i][2], s[i][3]));
#pragma unroll
            for (int off = 1; off < 16; off <<= 1)
                rm = fmaxf(rm, __shfl_xor_sync(0xffffffffu, rm, off));
            float mn = fmaxf(m_i[i], rm);
            float alpha = __expf(m_i[i] - mn);
            float rs = 0.0f;
#pragma unroll
            for (int c = 0; c < 4; c++) {
                float p = __expf(s[i][c] - mn);
                s[i][c] = p;
                rs += p;
            }
#pragma unroll
            for (int off = 1; off < 16; off <<= 1)
                rs += __shfl_xor_sync(0xffffffffu, rs, off);
            l_i[i] = l_i[i] * alpha + rs;
#pragma unroll
            for (int c = 0; c < 4; c++) o[i][c] *= alpha;
            m_i[i] = mn;
        }

        // write P (rows owned warp-locally: all threads of a ty are in one warp)
#pragma unroll
        for (int i = 0; i < 4; i++)
            *(float4*)&p_s[(4 * ty + i) * 64 + 4 * tx] =
                make_float4(s[i][0], s[i][1], s[i][2], s[i][3]);
        __syncwarp();

#pragma unroll 8
        for (int j = 0; j < 64; j++) {
            float4 vb = *(const float4*)&v_s[j * 64 + 4 * tx];
            float br[4] = {vb.x, vb.y, vb.z, vb.w};
#pragma unroll
            for (int i = 0; i < 4; i++) {
                float p = p_s[(4 * ty + i) * 64 + j];
#pragma unroll
                for (int c = 0; c < 4; c++)
                    o[i][c] = fmaf(p, br[c], o[i][c]);
            }
        }
    }

    // epilogue: O[b, s, h, d]
    const int b = bh >> 4;
    const int h = bh & 15;
#pragma unroll
    for (int i = 0; i < 4; i++) {
        float inv_l = 1.0f / l_i[i];
        int sg = qt * 64 + 4 * ty + i;
        size_t dst = (((size_t)b * S_LEN + sg) * NH + h) * HD + 4 * tx;
        *(float4*)&O[dst] = make_float4(o[i][0] * inv_l, o[i][1] * inv_l,
                                        o[i][2] * inv_l, o[i][3] * inv_l);
    }
}

// ---------------------------------------------------------------------------
extern "C" void kernel_launch(void* const* d_in, const int* in_sizes, int n_in,
                              void* d_out, int out_size)
{
    const float* x  = (const float*)d_in[0];
    const float* Wq = (const float*)d_in[1];
    const float* Wk = (const float*)d_in[2];
    const float* Wv = (const float*)d_in[3];
    const float* Wo = (const float*)d_in[4];
    float* out = (float*)d_out;

    float *q, *k, *v, *att;
    cudaGetSymbolAddress((void**)&q,   g_q);
    cudaGetSymbolAddress((void**)&k,   g_k);
    cudaGetSymbolAddress((void**)&v,   g_v);
    cudaGetSymbolAddress((void**)&att, g_att);

    dim3 ggrid(EMB / 128, M_TOK / 128);   // (8, 32)
    sgemm_nt<<<ggrid, 256>>>(x, Wq, q, M_TOK, EMB, EMB, 1);
    sgemm_nt<<<ggrid, 256>>>(x, Wk, k, M_TOK, EMB, EMB, 1);
    sgemm_nt<<<ggrid, 256>>>(x, Wv, v, M_TOK, EMB, EMB, 1);

    rope_kernel<<<(BATCH * NH * S_LEN * 32) / 256, 256>>>(q, k);

    cudaFuncSetAttribute(flash_kernel,
                         cudaFuncAttributeMaxDynamicSharedMemorySize, 65536);
    flash_kernel<<<dim3(S_LEN / 64, BATCH * NH), 256, 65536>>>(q, k, v, att);

    sgemm_nt<<<ggrid, 256>>>(att, Wo, out, M_TOK, EMB, EMB, 0);
}

// round 4
// speedup vs baseline: 3.8592x; 3.8592x over previous
#include <cuda_runtime.h>
#include <math.h>
#include <stdint.h>

#define S_LEN 2048
#define EMB   1024
#define NH    16
#define HD    64
#define BATCH 2
#define M_TOK (BATCH * S_LEN)   // 4096

// ---------------- scratch (device globals) ---------------------------------
__device__ float g_q[BATCH * NH * S_LEN * HD];    // [B,H,S,D]
__device__ float g_k[BATCH * NH * S_LEN * HD];    // [B,H,S,D]
__device__ float g_vt[BATCH * NH * HD * S_LEN];   // [B,H,D,S]  (V transposed)
__device__ float g_att[M_TOK * EMB];              // [B,S,E]

// ---------------- PTX helpers ----------------------------------------------
__device__ __forceinline__ uint32_t smem_u32(const void* p) {
    uint32_t a;
    asm("{ .reg .u64 t; cvta.to.shared.u64 t, %1; cvt.u32.u64 %0, t; }"
        : "=r"(a) : "l"(p));
    return a;
}
__device__ __forceinline__ void cp16(uint32_t s, const void* g) {
    asm volatile("cp.async.cg.shared.global [%0], [%1], 16;" :: "r"(s), "l"(g) : "memory");
}
__device__ __forceinline__ void cp_commit() {
    asm volatile("cp.async.commit_group;" ::: "memory");
}
#define CP_WAIT(n) asm volatile("cp.async.wait_group %0;" :: "n"(n) : "memory")

__device__ __forceinline__ void ldsm4(uint32_t* r, uint32_t addr) {
    asm volatile("ldmatrix.sync.aligned.m8n8.x4.shared.b16 {%0,%1,%2,%3}, [%4];"
                 : "=r"(r[0]), "=r"(r[1]), "=r"(r[2]), "=r"(r[3]) : "r"(addr));
}
__device__ __forceinline__ uint32_t f2tf(float f) {
    uint32_t u;
    asm("cvt.rna.tf32.f32 %0, %1;" : "=r"(u) : "f"(f));
    return u;
}
__device__ __forceinline__ void mma_tf32(float* c, const uint32_t* a,
                                         uint32_t b0, uint32_t b1) {
    asm volatile(
        "mma.sync.aligned.m16n8k8.row.col.f32.tf32.tf32.f32 "
        "{%0,%1,%2,%3}, {%4,%5,%6,%7}, {%8,%9}, {%0,%1,%2,%3};"
        : "+f"(c[0]), "+f"(c[1]), "+f"(c[2]), "+f"(c[3])
        : "r"(a[0]), "r"(a[1]), "r"(a[2]), "r"(a[3]), "r"(b0), "r"(b1));
}
__device__ __forceinline__ void sts64(uint32_t addr, uint32_t u0, uint32_t u1) {
    asm volatile("st.shared.v2.b32 [%0], {%1,%2};" :: "r"(addr), "r"(u0), "r"(u1) : "memory");
}

// ---------------------------------------------------------------------------
// tf32 mma GEMM: C[M=4096, N=1024] = A[4096,1024] @ W[1024,1024]^T
// CTA 128x128, 8 warps (warp tile 64x32), KC=32, 3-stage cp.async pipeline.
// mode 0: row-major [M,1024]; mode 1: scatter [B,H,S,D]; mode 2: [B,H,D,S].
// ---------------------------------------------------------------------------
#define GST 3
#define GSMEM (GST * 32768)

__global__ __launch_bounds__(256, 1) void gemm_mma(const float* __restrict__ A,
                                                   const float* __restrict__ W,
                                                   float* __restrict__ C, int mode)
{
    extern __shared__ char smx[];
    const uint32_t sb = smem_u32(smx);
    const int tid = threadIdx.x, wid = tid >> 5, lane = tid & 31;
    const int bn0 = blockIdx.x * 128, bm0 = blockIdx.y * 128;
    const int wm = (wid & 1) * 64, wn = (wid >> 1) * 32;

    // fragment address lane components
    const int matq   = lane >> 3;
    const int arow_l = ((matq & 1) << 3) + (lane & 7);
    const int ac16_l = matq >> 1;
    const int brow_l = ((matq >> 1) << 3) + (lane & 7);
    const int bc16_l = matq & 1;

    auto load = [&](int ck, int st) {
        uint32_t Ab = sb + st * 32768, Bb = Ab + 16384;
#pragma unroll
        for (int j = 0; j < 4; j++) {
            int idx = tid + j * 256;
            int r = idx >> 3, c16 = idx & 7;
            uint32_t sw = (uint32_t)(r * 128) + (uint32_t)((c16 ^ (r & 7)) << 4);
            cp16(Ab + sw, A + (size_t)(bm0 + r) * 1024 + ck * 32 + c16 * 4);
            cp16(Bb + sw, W + (size_t)(bn0 + r) * 1024 + ck * 32 + c16 * 4);
        }
        cp_commit();
    };
    load(0, 0); load(1, 1); load(2, 2);

    float acc[4][4][4];
#pragma unroll
    for (int f = 0; f < 4; f++)
#pragma unroll
        for (int n = 0; n < 4; n++)
#pragma unroll
            for (int i = 0; i < 4; i++) acc[f][n][i] = 0.0f;

    for (int c = 0; c < 32; c++) {
        int st = c % 3;
        if (c < 30) { CP_WAIT(2); }
        else if (c == 30) { CP_WAIT(1); }
        else { CP_WAIT(0); }
        __syncthreads();

        uint32_t Ab = sb + st * 32768, Bb = Ab + 16384;
#pragma unroll
        for (int s = 0; s < 4; s++) {
            uint32_t af[4][4];
#pragma unroll
            for (int f = 0; f < 4; f++) {
                int row = wm + f * 16 + arow_l;
                int c16 = ac16_l + 2 * s;
                ldsm4(af[f], Ab + row * 128 + ((c16 ^ (row & 7)) << 4));
#pragma unroll
                for (int i = 0; i < 4; i++)
                    af[f][i] = f2tf(__uint_as_float(af[f][i]));
            }
#pragma unroll
            for (int p = 0; p < 2; p++) {
                uint32_t bf[4];
                int row = wn + p * 16 + brow_l;
                int c16 = bc16_l + 2 * s;
                ldsm4(bf, Bb + row * 128 + ((c16 ^ (row & 7)) << 4));
#pragma unroll
                for (int i = 0; i < 4; i++)
                    bf[i] = f2tf(__uint_as_float(bf[i]));
#pragma unroll
                for (int f = 0; f < 4; f++) {
                    mma_tf32(acc[f][2 * p],     af[f], bf[0], bf[1]);
                    mma_tf32(acc[f][2 * p + 1], af[f], bf[2], bf[3]);
                }
            }
        }
        __syncthreads();
        if (c + 3 < 32) load(c + 3, st);
    }

    // epilogue: direct global stores from c-frags
#pragma unroll
    for (int f = 0; f < 4; f++) {
        int m0 = bm0 + wm + f * 16 + (lane >> 2);
#pragma unroll
        for (int nf = 0; nf < 4; nf++) {
            int n0 = bn0 + wn + nf * 8 + 2 * (lane & 3);
            if (mode == 0) {
                *(float2*)&C[(size_t)m0 * 1024 + n0] =
                    make_float2(acc[f][nf][0], acc[f][nf][1]);
                *(float2*)&C[(size_t)(m0 + 8) * 1024 + n0] =
                    make_float2(acc[f][nf][2], acc[f][nf][3]);
            } else if (mode == 1) {
                int h = n0 >> 6, d = n0 & 63;
#pragma unroll
                for (int rr = 0; rr < 2; rr++) {
                    int m = m0 + 8 * rr;
                    int b = m >> 11, s2 = m & 2047;
                    *(float2*)&C[((((size_t)(b * NH + h) * S_LEN + s2)) << 6) + d] =
                        make_float2(acc[f][nf][rr * 2], acc[f][nf][rr * 2 + 1]);
                }
            } else {
                int h = n0 >> 6, d = n0 & 63;
#pragma unroll
                for (int rr = 0; rr < 2; rr++) {
                    int m = m0 + 8 * rr;
                    int b = m >> 11, s2 = m & 2047;
                    size_t base = (((size_t)(b * NH + h) * HD + d) << 11) + s2;
                    C[base]        = acc[f][nf][rr * 2];
                    C[base + 2048] = acc[f][nf][rr * 2 + 1];
                }
            }
        }
    }
}

// ---------------------------------------------------------------------------
// RoPE in-place on q,k ([B,H,S,D]); pair (d, d+32).
// ---------------------------------------------------------------------------
__global__ __launch_bounds__(256) void rope_kernel(float* __restrict__ q,
                                                   float* __restrict__ k)
{
    int t = blockIdx.x * blockDim.x + threadIdx.x;
    int i  = t & 31;
    int s  = (t >> 5) & (S_LEN - 1);
    int bh = t >> 16;
    float inv_freq = powf(10000.0f, -(float)i * (1.0f / 32.0f));
    float theta = (float)s * inv_freq;
    float sn, cs;
    sincosf(theta, &sn, &cs);
    size_t base = ((size_t)bh * S_LEN + s) * HD;
    float q1 = q[base + i], q2 = q[base + i + 32];
    q[base + i]      = q1 * cs - q2 * sn;
    q[base + i + 32] = q2 * cs + q1 * sn;
    float k1 = k[base + i], k2 = k[base + i + 32];
    k[base + i]      = k1 * cs - k2 * sn;
    k[base + i + 32] = k2 * cs + k1 * sn;
}

// ---------------------------------------------------------------------------
// Causal flash attention with tf32 mma.sync.
// CTA: 128 q-rows (8 warps x 16), K/V tiles 64 wide, double-buffered cp.async.
// V consumed from pre-transposed g_vt [B,H,D,S]. Output -> att [B,S,E].
// smem: Q 32KB | K 2x16KB | V 2x16KB | P 8x4KB  = 128KB
// ---------------------------------------------------------------------------
#define FSMEM (32768 + 32768 + 32768 + 32768)

__global__ __launch_bounds__(256, 1) void flash_mma(const float* __restrict__ Q,
                                                    const float* __restrict__ K,
                                                    const float* __restrict__ Vt,
                                                    float* __restrict__ O)
{
    extern __shared__ char smx[];
    const uint32_t sb = smem_u32(smx);
    const int tid = threadIdx.x, wid = tid >> 5, lane = tid & 31;
    const int qt = blockIdx.x, bh = blockIdx.y;

    const uint32_t Qs  = sb;
    const uint32_t Ks0 = sb + 32768;
    const uint32_t Vs0 = sb + 65536;
    const uint32_t Pw  = sb + 98304 + wid * 4096;

    const float* Qg = Q  + ((size_t)bh * S_LEN + qt * 128) * HD;
    const float* Kg = K  + (size_t)bh * S_LEN * HD;
    const float* Vg = Vt + (size_t)bh * HD * S_LEN;

    const int matq   = lane >> 3;
    const int arow_l = ((matq & 1) << 3) + (lane & 7);
    const int ac16_l = matq >> 1;
    const int brow_l = ((matq >> 1) << 3) + (lane & 7);
    const int bc16_l = matq & 1;

    auto loadKV = [&](int kt, int st) {
#pragma unroll
        for (int j = 0; j < 4; j++) {
            int idx = tid + j * 256;
            int r = idx >> 4, c16 = idx & 15;
            uint32_t sw = (uint32_t)(r * 256) + (uint32_t)((c16 ^ (r & 7)) << 4);
            cp16(Ks0 + st * 16384 + sw, Kg + (size_t)(kt * 64 + r) * HD + c16 * 4);
            cp16(Vs0 + st * 16384 + sw, Vg + (size_t)r * S_LEN + kt * 64 + c16 * 4);
        }
    };

    // group 0: Q tile + KV tile 0
#pragma unroll
    for (int j = 0; j < 8; j++) {
        int idx = tid + j * 256;
        int r = idx >> 4, c16 = idx & 15;
        uint32_t sw = (uint32_t)(r * 256) + (uint32_t)((c16 ^ (r & 7)) << 4);
        cp16(Qs + sw, Qg + (size_t)r * HD + c16 * 4);
    }
    loadKV(0, 0);
    cp_commit();

    const int ktmax = 2 * qt + 1;
    uint32_t qf[8][4];
    float accO[8][4];
#pragma unroll
    for (int d = 0; d < 8; d++)
#pragma unroll
        for (int i = 0; i < 4; i++) accO[d][i] = 0.0f;
    float m_r[2] = {-1e30f, -1e30f};
    float l_r[2] = {0.0f, 0.0f};

    for (int kt = 0; kt <= ktmax; kt++) {
        const int st = kt & 1;
        if (kt < ktmax) { loadKV(kt + 1, st ^ 1); cp_commit(); CP_WAIT(1); }
        else            { CP_WAIT(0); }
        __syncthreads();

        if (kt == 0) {
#pragma unroll
            for (int s = 0; s < 8; s++) {
                int row = wid * 16 + arow_l;
                int c16 = ac16_l + 2 * s;
                ldsm4(qf[s], Qs + row * 256 + ((c16 ^ (row & 7)) << 4));
#pragma unroll
                for (int i = 0; i < 4; i++)
                    qf[s][i] = f2tf(__uint_as_float(qf[s][i]) * 0.125f);
            }
        }

        const uint32_t Kst = Ks0 + st * 16384;
        const uint32_t Vst = Vs0 + st * 16384;

        // ---- S = Q @ K^T -------------------------------------------------
        float S[8][4];
#pragma unroll
        for (int n = 0; n < 8; n++)
#pragma unroll
            for (int i = 0; i < 4; i++) S[n][i] = 0.0f;

#pragma unroll
        for (int s = 0; s < 8; s++) {
#pragma unroll
            for (int p = 0; p < 4; p++) {
                uint32_t bf[4];
                int row = p * 16 + brow_l;
                int c16 = bc16_l + 2 * s;
                ldsm4(bf, Kst + row * 256 + ((c16 ^ (row & 7)) << 4));
#pragma unroll
                for (int i = 0; i < 4; i++)
                    bf[i] = f2tf(__uint_as_float(bf[i]));
                mma_tf32(S[2 * p],     qf[s], bf[0], bf[1]);
                mma_tf32(S[2 * p + 1], qf[s], bf[2], bf[3]);
            }
        }

        // ---- causal mask (only the two diagonal-touching tiles) ----------
        if (kt >= 2 * qt) {
            int rbase = qt * 128 + wid * 16 + (lane >> 2);
#pragma unroll
            for (int nf = 0; nf < 8; nf++) {
                int cc = kt * 64 + nf * 8 + 2 * (lane & 3);
                if (cc     > rbase)     S[nf][0] = -1e30f;
                if (cc + 1 > rbase)     S[nf][1] = -1e30f;
                if (cc     > rbase + 8) S[nf][2] = -1e30f;
                if (cc + 1 > rbase + 8) S[nf][3] = -1e30f;
            }
        }

        // ---- online softmax ----------------------------------------------
#pragma unroll
        for (int rh = 0; rh < 2; rh++) {
            float mx = -1e30f;
#pragma unroll
            for (int nf = 0; nf < 8; nf++)
                mx = fmaxf(mx, fmaxf(S[nf][rh * 2], S[nf][rh * 2 + 1]));
            mx = fmaxf(mx, __shfl_xor_sync(0xffffffffu, mx, 1));
            mx = fmaxf(mx, __shfl_xor_sync(0xffffffffu, mx, 2));
            float mn = fmaxf(m_r[rh], mx);
            float alpha = __expf(m_r[rh] - mn);
            float sum = 0.0f;
#pragma unroll
            for (int nf = 0; nf < 8; nf++) {
                float p0 = __expf(S[nf][rh * 2]     - mn);
                float p1 = __expf(S[nf][rh * 2 + 1] - mn);
                S[nf][rh * 2] = p0; S[nf][rh * 2 + 1] = p1;
                sum += p0 + p1;
            }
            sum += __shfl_xor_sync(0xffffffffu, sum, 1);
            sum += __shfl_xor_sync(0xffffffffu, sum, 2);
            l_r[rh] = l_r[rh] * alpha + sum;
            m_r[rh] = mn;
#pragma unroll
            for (int df = 0; df < 8; df++) {
                accO[df][rh * 2]     *= alpha;
                accO[df][rh * 2 + 1] *= alpha;
            }
        }

        // ---- P -> smem (tf32-rounded) ------------------------------------
        {
            int pc = 2 * (lane & 3);
            int off = (pc * 4) & 15;         // 0 or 8
            int c16b = (pc >= 4) ? 1 : 0;
#pragma unroll
            for (int nf = 0; nf < 8; nf++) {
#pragma unroll
                for (int rh = 0; rh < 2; rh++) {
                    int row = (lane >> 2) + rh * 8;
                    int c16 = nf * 2 + c16b;
                    uint32_t addr = Pw + row * 256 + ((c16 ^ (row & 7)) << 4) + off;
                    sts64(addr, f2tf(S[nf][rh * 2]), f2tf(S[nf][rh * 2 + 1]));
                }
            }
        }
        __syncwarp();

        // ---- O += P @ V --------------------------------------------------
#pragma unroll
        for (int s = 0; s < 8; s++) {
            uint32_t pa[4];
            {
                int row = arow_l;
                int c16 = ac16_l + 2 * s;
                ldsm4(pa, Pw + row * 256 + ((c16 ^ (row & 7)) << 4));
            }
#pragma unroll
            for (int p = 0; p < 4; p++) {
                uint32_t bf[4];
                int row = p * 16 + brow_l;
                int c16 = bc16_l + 2 * s;
                ldsm4(bf, Vst + row * 256 + ((c16 ^ (row & 7)) << 4));
#pragma unroll
                for (int i = 0; i < 4; i++)
                    bf[i] = f2tf(__uint_as_float(bf[i]));
                mma_tf32(accO[2 * p],     pa, bf[0], bf[1]);
                mma_tf32(accO[2 * p + 1], pa, bf[2], bf[3]);
            }
        }
        __syncthreads();
    }

    // ---- epilogue: att [B,S,E] -------------------------------------------
    float inv0 = 1.0f / l_r[0], inv1 = 1.0f / l_r[1];
    int b = bh >> 4, h = bh & 15;
    int r0 = qt * 128 + wid * 16 + (lane >> 2);
#pragma unroll
    for (int df = 0; df < 8; df++) {
        int d = df * 8 + 2 * (lane & 3);
        size_t a0 = ((size_t)(b * S_LEN + r0)) * EMB + h * 64 + d;
        *(float2*)&O[a0] = make_float2(accO[df][0] * inv0, accO[df][1] * inv0);
        *(float2*)&O[a0 + (size_t)8 * EMB] =
            make_float2(accO[df][2] * inv1, accO[df][3] * inv1);
    }
}

// ---------------------------------------------------------------------------
extern "C" void kernel_launch(void* const* d_in, const int* in_sizes, int n_in,
                              void* d_out, int out_size)
{
    const float* x  = (const float*)d_in[0];
    const float* Wq = (const float*)d_in[1];
    const float* Wk = (const float*)d_in[2];
    const float* Wv = (const float*)d_in[3];
    const float* Wo = (const float*)d_in[4];
    float* out = (float*)d_out;

    float *q, *k, *vt, *att;
    cudaGetSymbolAddress((void**)&q,   g_q);
    cudaGetSymbolAddress((void**)&k,   g_k);
    cudaGetSymbolAddress((void**)&vt,  g_vt);
    cudaGetSymbolAddress((void**)&att, g_att);

    cudaFuncSetAttribute(gemm_mma, cudaFuncAttributeMaxDynamicSharedMemorySize, GSMEM);
    cudaFuncSetAttribute(flash_mma, cudaFuncAttributeMaxDynamicSharedMemorySize, FSMEM);

    dim3 ggrid(EMB / 128, M_TOK / 128);   // (8, 32)
    gemm_mma<<<ggrid, 256, GSMEM>>>(x, Wq, q, 1);
    gemm_mma<<<ggrid, 256, GSMEM>>>(x, Wk, k, 1);
    gemm_mma<<<ggrid, 256, GSMEM>>>(x, Wv, vt, 2);

    rope_kernel<<<(BATCH * NH * S_LEN * 32) / 256, 256>>>(q, k);

    flash_mma<<<dim3(S_LEN / 128, BATCH * NH), 256, FSMEM>>>(q, k, vt, att);

    gemm_mma<<<ggrid, 256, GSMEM>>>(att, Wo, out, 0);
}

// round 6
// speedup vs baseline: 7.6164x; 1.9736x over previous
#include <cuda_runtime.h>
#include <cuda_fp16.h>
#include <math.h>
#include <stdint.h>

#define S_LEN 2048
#define EMB   1024
#define NH    16
#define HD    64
#define BATCH 2
#define M_TOK (BATCH * S_LEN)   // 4096

// ---------------- scratch (device globals) ---------------------------------
__device__ float  g_q [BATCH * NH * S_LEN * HD];  // fp32 [B,H,S,D]
__device__ float  g_k [BATCH * NH * S_LEN * HD];
__device__ __half g_qh[BATCH * NH * S_LEN * HD];  // half, RoPE'd + pre-scaled
__device__ __half g_kh[BATCH * NH * S_LEN * HD];  // half, RoPE'd
__device__ __half g_vh[BATCH * NH * S_LEN * HD];  // half [B,H,S,D]
__device__ __half g_xh[(size_t)M_TOK * EMB];      // half x
__device__ __half g_wh[4 * EMB * EMB];            // half Wq|Wk|Wv|Wo
__device__ __half g_atth[(size_t)M_TOK * EMB];    // half attention out [B,S,E]

// ---------------- PTX helpers ----------------------------------------------
__device__ __forceinline__ uint32_t smem_u32(const void* p) {
    uint32_t a;
    asm("{ .reg .u64 t; cvta.to.shared.u64 t, %1; cvt.u32.u64 %0, t; }"
        : "=r"(a) : "l"(p));
    return a;
}
__device__ __forceinline__ void cp16(uint32_t s, const void* g) {
    asm volatile("cp.async.cg.shared.global [%0], [%1], 16;" :: "r"(s), "l"(g) : "memory");
}
__device__ __forceinline__ void cp_commit() {
    asm volatile("cp.async.commit_group;" ::: "memory");
}
#define CP_WAIT(n) asm volatile("cp.async.wait_group %0;" :: "n"(n) : "memory")

__device__ __forceinline__ void ldsm4(uint32_t* r, uint32_t addr) {
    asm volatile("ldmatrix.sync.aligned.m8n8.x4.shared.b16 {%0,%1,%2,%3}, [%4];"
                 : "=r"(r[0]), "=r"(r[1]), "=r"(r[2]), "=r"(r[3]) : "r"(addr));
}
__device__ __forceinline__ void ldsm4t(uint32_t* r, uint32_t addr) {
    asm volatile("ldmatrix.sync.aligned.m8n8.x4.trans.shared.b16 {%0,%1,%2,%3}, [%4];"
                 : "=r"(r[0]), "=r"(r[1]), "=r"(r[2]), "=r"(r[3]) : "r"(addr));
}
__device__ __forceinline__ void mma_h(float* c, const uint32_t* a,
                                      uint32_t b0, uint32_t b1) {
    asm volatile(
        "mma.sync.aligned.m16n8k16.row.col.f32.f16.f16.f32 "
        "{%0,%1,%2,%3}, {%4,%5,%6,%7}, {%8,%9}, {%0,%1,%2,%3};"
        : "+f"(c[0]), "+f"(c[1]), "+f"(c[2]), "+f"(c[3])
        : "r"(a[0]), "r"(a[1]), "r"(a[2]), "r"(a[3]), "r"(b0), "r"(b1));
}
__device__ __forceinline__ uint32_t pack2(float a, float b) {
    __half2 h = __floats2half2_rn(a, b);
    return *reinterpret_cast<uint32_t*>(&h);
}

// ---------------------------------------------------------------------------
// fp32 -> half converter (vectorized x4)
// ---------------------------------------------------------------------------
__global__ __launch_bounds__(256) void conv_h(const float* __restrict__ in,
                                              __half* __restrict__ out)
{
    int idx = (blockIdx.x * 256 + threadIdx.x) * 4;
    float4 v = *(const float4*)&in[idx];
    uint2 u;
    u.x = pack2(v.x, v.y);
    u.y = pack2(v.z, v.w);
    *(uint2*)&out[idx] = u;
}

// ---------------------------------------------------------------------------
// half mma GEMM: C[4096,1024] = A[4096,1024] @ W[1024,1024]^T (fp32 accum)
// CTA 128x128, 8 warps (warp 64x32), k-chunk 64, 3-stage cp.async pipeline.
// mode 0: fp32 row-major [M,1024]; mode 1: fp32 scatter [B,H,S,D];
// mode 2: half scatter [B,H,S,D].
// ---------------------------------------------------------------------------
#define GSMEM (3 * 32768)

__global__ __launch_bounds__(256, 2) void gemm_h(const __half* __restrict__ A,
                                                 const __half* __restrict__ W,
                                                 float* __restrict__ Cf,
                                                 __half* __restrict__ Ch, int mode)
{
    extern __shared__ char smx[];
    const uint32_t sb = smem_u32(smx);
    const int tid = threadIdx.x, wid = tid >> 5, lane = tid & 31;
    const int bn0 = blockIdx.x * 128, bm0 = blockIdx.y * 128;
    const int wm = (wid & 1) * 64, wn = (wid >> 1) * 32;

    const int g = lane >> 3;
    const int arow = (g & 1) * 8 + (lane & 7);
    const int ac16 = g >> 1;
    const int brow = (g >> 1) * 8 + (lane & 7);
    const int bc16 = g & 1;

    auto load = [&](int ck, int st) {
        uint32_t Ab = sb + st * 32768, Bb = Ab + 16384;
#pragma unroll
        for (int j = 0; j < 4; j++) {
            int idx = tid + j * 256;
            int r = idx >> 3, c16 = idx & 7;
            uint32_t sw = (uint32_t)(r * 128) + (uint32_t)((c16 ^ (r & 7)) << 4);
            cp16(Ab + sw, A + (size_t)(bm0 + r) * 1024 + ck * 64 + c16 * 8);
            cp16(Bb + sw, W + (size_t)(bn0 + r) * 1024 + ck * 64 + c16 * 8);
        }
        cp_commit();
    };
    load(0, 0); load(1, 1); load(2, 2);

    float acc[4][4][4];
#pragma unroll
    for (int f = 0; f < 4; f++)
#pragma unroll
        for (int n = 0; n < 4; n++)
#pragma unroll
            for (int i = 0; i < 4; i++) acc[f][n][i] = 0.0f;

    for (int c = 0; c < 16; c++) {
        int st = c % 3;
        if (c < 14)      { CP_WAIT(2); }
        else if (c == 14){ CP_WAIT(1); }
        else             { CP_WAIT(0); }
        __syncthreads();

        uint32_t Ab = sb + st * 32768, Bb = Ab + 16384;
#pragma unroll
        for (int ks = 0; ks < 4; ks++) {
            uint32_t af[4][4];
#pragma unroll
            for (int mb = 0; mb < 4; mb++) {
                int row = wm + mb * 16 + arow;
                ldsm4(af[mb], Ab + row * 128 + (((2 * ks + ac16) ^ (row & 7)) << 4));
            }
#pragma unroll
            for (int pn = 0; pn < 2; pn++) {
                uint32_t bf[4];
                int rowb = wn + pn * 16 + brow;
                ldsm4(bf, Bb + rowb * 128 + (((2 * ks + bc16) ^ (rowb & 7)) << 4));
#pragma unroll
                for (int mb = 0; mb < 4; mb++) {
                    mma_h(acc[mb][2 * pn],     af[mb], bf[0], bf[1]);
                    mma_h(acc[mb][2 * pn + 1], af[mb], bf[2], bf[3]);
                }
            }
        }
        __syncthreads();
        if (c + 3 < 16) load(c + 3, st);
    }

    // ---- epilogue ----------------------------------------------------------
#pragma unroll
    for (int f = 0; f < 4; f++) {
        int m0 = bm0 + wm + f * 16 + (lane >> 2);
#pragma unroll
        for (int nf = 0; nf < 4; nf++) {
            int n0 = bn0 + wn + nf * 8 + 2 * (lane & 3);
            if (mode == 0) {
                *(float2*)&Cf[(size_t)m0 * 1024 + n0] =
                    make_float2(acc[f][nf][0], acc[f][nf][1]);
                *(float2*)&Cf[(size_t)(m0 + 8) * 1024 + n0] =
                    make_float2(acc[f][nf][2], acc[f][nf][3]);
            } else {
                int h = n0 >> 6, d = n0 & 63;
#pragma unroll
                for (int rr = 0; rr < 2; rr++) {
                    int m = m0 + 8 * rr;
                    int b = m >> 11, s2 = m & 2047;
                    size_t dst = ((((size_t)(b * NH + h) * S_LEN + s2)) << 6) + d;
                    if (mode == 1) {
                        *(float2*)&Cf[dst] =
                            make_float2(acc[f][nf][rr * 2], acc[f][nf][rr * 2 + 1]);
                    } else {
                        uint32_t h2 = pack2(acc[f][nf][rr * 2], acc[f][nf][rr * 2 + 1]);
                        *(uint32_t*)&Ch[dst] = h2;
                    }
                }
            }
        }
    }
}

// ---------------------------------------------------------------------------
// RoPE: fp32 q,k -> half qh (pre-scaled by 1/8), kh. Pair (d, d+32).
// ---------------------------------------------------------------------------
__global__ __launch_bounds__(256) void rope_h(const float* __restrict__ q,
                                              const float* __restrict__ k,
                                              __half* __restrict__ qh,
                                              __half* __restrict__ kh)
{
    int t = blockIdx.x * blockDim.x + threadIdx.x;
    int i  = t & 31;
    int s  = (t >> 5) & (S_LEN - 1);
    int bh = t >> 16;
    float inv_freq = powf(10000.0f, -(float)i * (1.0f / 32.0f));
    float theta = (float)s * inv_freq;
    float sn, cs;
    sincosf(theta, &sn, &cs);
    size_t base = ((size_t)bh * S_LEN + s) * HD;
    float q1 = q[base + i], q2 = q[base + i + 32];
    qh[base + i]      = __float2half((q1 * cs - q2 * sn) * 0.125f);
    qh[base + i + 32] = __float2half((q2 * cs + q1 * sn) * 0.125f);
    float k1 = k[base + i], k2 = k[base + i + 32];
    kh[base + i]      = __float2half(k1 * cs - k2 * sn);
    kh[base + i + 32] = __float2half(k2 * cs + k1 * sn);
}

// ---------------------------------------------------------------------------
// Causal flash attention, fp16 mma, P kept in registers (C-frag -> A-frag).
// CTA: 128 q rows (8 warps x 16), KV tiles 64, double-buffered cp.async.
// V from [B,H,S,D] via ldmatrix.trans. Output half att [B,S,E].
// smem: Q 16KB | K 2x8KB | V 2x8KB = 48KB
// ---------------------------------------------------------------------------
#define FSMEM (16384 + 16384 + 16384)

__global__ __launch_bounds__(256, 2) void flash_h(const __half* __restrict__ Q,
                                                  const __half* __restrict__ K,
                                                  const __half* __restrict__ V,
                                                  __half* __restrict__ O)
{
    extern __shared__ char smx[];
    const uint32_t sb = smem_u32(smx);
    const int tid = threadIdx.x, wid = tid >> 5, lane = tid & 31;
    const int qt = gridDim.x - 1 - blockIdx.x;   // largest tiles first
    const int bh = blockIdx.y;

    const uint32_t Qs  = sb;
    const uint32_t Ks0 = sb + 16384;
    const uint32_t Vs0 = sb + 32768;

    const __half* Qg = Q + ((size_t)bh * S_LEN + qt * 128) * HD;
    const __half* Kg = K + (size_t)bh * S_LEN * HD;
    const __half* Vg = V + (size_t)bh * S_LEN * HD;

    const int g = lane >> 3;
    const int arow = (g & 1) * 8 + (lane & 7);
    const int ac16 = g >> 1;
    const int brow = (g >> 1) * 8 + (lane & 7);
    const int bc16 = g & 1;

    auto loadKV = [&](int kt, int st) {
#pragma unroll
        for (int j = 0; j < 2; j++) {
            int idx = tid + j * 256;            // 0..511
            int r = idx >> 3, c16 = idx & 7;
            uint32_t sw = (uint32_t)(r * 128) + (uint32_t)((c16 ^ (r & 7)) << 4);
            cp16(Ks0 + st * 8192 + sw, Kg + (size_t)(kt * 64 + r) * HD + c16 * 8);
            cp16(Vs0 + st * 8192 + sw, Vg + (size_t)(kt * 64 + r) * HD + c16 * 8);
        }
    };

    // group 0: Q tile + KV tile 0
#pragma unroll
    for (int j = 0; j < 4; j++) {
        int idx = tid + j * 256;                // 0..1023
        int r = idx >> 3, c16 = idx & 7;
        uint32_t sw = (uint32_t)(r * 128) + (uint32_t)((c16 ^ (r & 7)) << 4);
        cp16(Qs + sw, Qg + (size_t)r * HD + c16 * 8);
    }
    loadKV(0, 0);
    cp_commit();

    const int ktmax = 2 * qt + 1;
    uint32_t qf[4][4];
    float accO[8][4];
#pragma unroll
    for (int d = 0; d < 8; d++)
#pragma unroll
        for (int i = 0; i < 4; i++) accO[d][i] = 0.0f;
    float m_r[2] = {-1e30f, -1e30f};
    float l_r[2] = {0.0f, 0.0f};

    for (int kt = 0; kt <= ktmax; kt++) {
        const int st = kt & 1;
        if (kt < ktmax) { loadKV(kt + 1, st ^ 1); cp_commit(); CP_WAIT(1); }
        else            { CP_WAIT(0); }
        __syncthreads();

        if (kt == 0) {
#pragma unroll
            for (int ks = 0; ks < 4; ks++) {
                int row = wid * 16 + arow;
                ldsm4(qf[ks], Qs + row * 128 + (((2 * ks + ac16) ^ (row & 7)) << 4));
            }
        }

        const uint32_t Kst = Ks0 + st * 8192;
        const uint32_t Vst = Vs0 + st * 8192;

        // ---- S = Q @ K^T -------------------------------------------------
        float S[8][4];
#pragma unroll
        for (int n = 0; n < 8; n++)
#pragma unroll
            for (int i = 0; i < 4; i++) S[n][i] = 0.0f;

#pragma unroll
        for (int ks = 0; ks < 4; ks++) {
#pragma unroll
            for (int pn = 0; pn < 4; pn++) {
                uint32_t bf[4];
                int rowb = pn * 16 + brow;
                ldsm4(bf, Kst + rowb * 128 + (((2 * ks + bc16) ^ (rowb & 7)) << 4));
                mma_h(S[2 * pn],     qf[ks], bf[0], bf[1]);
                mma_h(S[2 * pn + 1], qf[ks], bf[2], bf[3]);
            }
        }

        // ---- causal mask (only the two diagonal-touching tiles) ----------
        if (kt >= 2 * qt) {
            int rbase = qt * 128 + wid * 16 + (lane >> 2);
#pragma unroll
            for (int nf = 0; nf < 8; nf++) {
                int cc = kt * 64 + nf * 8 + 2 * (lane & 3);
                if (cc     > rbase)     S[nf][0] = -1e30f;
                if (cc + 1 > rbase)     S[nf][1] = -1e30f;
                if (cc     > rbase + 8) S[nf][2] = -1e30f;
                if (cc + 1 > rbase + 8) S[nf][3] = -1e30f;
            }
        }

        // ---- online softmax ----------------------------------------------
#pragma unroll
        for (int rh = 0; rh < 2; rh++) {
            float mx = -1e30f;
#pragma unroll
            for (int nf = 0; nf < 8; nf++)
                mx = fmaxf(mx, fmaxf(S[nf][rh * 2], S[nf][rh * 2 + 1]));
            mx = fmaxf(mx, __shfl_xor_sync(0xffffffffu, mx, 1));
            mx = fmaxf(mx, __shfl_xor_sync(0xffffffffu, mx, 2));
            float mn = fmaxf(m_r[rh], mx);
            float alpha = __expf(m_r[rh] - mn);
            float sum = 0.0f;
#pragma unroll
            for (int nf = 0; nf < 8; nf++) {
                float p0 = __expf(S[nf][rh * 2]     - mn);
                float p1 = __expf(S[nf][rh * 2 + 1] - mn);
                S[nf][rh * 2] = p0; S[nf][rh * 2 + 1] = p1;
                sum += p0 + p1;
            }
            sum += __shfl_xor_sync(0xffffffffu, sum, 1);
            sum += __shfl_xor_sync(0xffffffffu, sum, 2);
            l_r[rh] = l_r[rh] * alpha + sum;
            m_r[rh] = mn;
#pragma unroll
            for (int df = 0; df < 8; df++) {
                accO[df][rh * 2]     *= alpha;
                accO[df][rh * 2 + 1] *= alpha;
            }
        }

        // ---- O += P @ V (P straight from registers) ----------------------
#pragma unroll
        for (int j = 0; j < 4; j++) {
            uint32_t pa[4];
            pa[0] = pack2(S[2 * j][0],     S[2 * j][1]);
            pa[1] = pack2(S[2 * j][2],     S[2 * j][3]);
            pa[2] = pack2(S[2 * j + 1][0], S[2 * j + 1][1]);
            pa[3] = pack2(S[2 * j + 1][2], S[2 * j + 1][3]);
#pragma unroll
            for (int pn = 0; pn < 4; pn++) {
                uint32_t bv[4];
                int rowv = j * 16 + arow;
                ldsm4t(bv, Vst + rowv * 128 + (((2 * pn + ac16) ^ (rowv & 7)) << 4));
                mma_h(accO[2 * pn],     pa, bv[0], bv[1]);
                mma_h(accO[2 * pn + 1], pa, bv[2], bv[3]);
            }
        }
        __syncthreads();
    }

    // ---- epilogue: half att [B,S,E] --------------------------------------
    float inv0 = 1.0f / l_r[0], inv1 = 1.0f / l_r[1];
    int b = bh >> 4, h = bh & 15;
    int r0 = qt * 128 + wid * 16 + (lane >> 2);
#pragma unroll
    for (int df = 0; df < 8; df++) {
        int d = df * 8 + 2 * (lane & 3);
        size_t a0 = ((size_t)(b * S_LEN + r0)) * EMB + h * 64 + d;
        *(uint32_t*)&O[a0] = pack2(accO[df][0] * inv0, accO[df][1] * inv0);
        *(uint32_t*)&O[a0 + (size_t)8 * EMB] =
            pack2(accO[df][2] * inv1, accO[df][3] * inv1);
    }
}

// ---------------------------------------------------------------------------
extern "C" void kernel_launch(void* const* d_in, const int* in_sizes, int n_in,
                              void* d_out, int out_size)
{
    const float* x  = (const float*)d_in[0];
    const float* Wq = (const float*)d_in[1];
    const float* Wk = (const float*)d_in[2];
    const float* Wv = (const float*)d_in[3];
    const float* Wo = (const float*)d_in[4];
    float* out = (float*)d_out;

    float *q, *k;
    __half *qh, *kh, *vh, *xh, *wh, *atth;
    cudaGetSymbolAddress((void**)&q,    g_q);
    cudaGetSymbolAddress((void**)&k,    g_k);
    cudaGetSymbolAddress((void**)&qh,   g_qh);
    cudaGetSymbolAddress((void**)&kh,   g_kh);
    cudaGetSymbolAddress((void**)&vh,   g_vh);
    cudaGetSymbolAddress((void**)&xh,   g_xh);
    cudaGetSymbolAddress((void**)&wh,   g_wh);
    cudaGetSymbolAddress((void**)&atth, g_atth);

    cudaFuncSetAttribute(gemm_h,  cudaFuncAttributeMaxDynamicSharedMemorySize, GSMEM);
    cudaFuncSetAttribute(flash_h, cudaFuncAttributeMaxDynamicSharedMemorySize, FSMEM);

    // fp32 -> half conversions
    conv_h<<<(M_TOK * EMB) / 1024, 256>>>(x,  xh);
    conv_h<<<(EMB * EMB) / 1024, 256>>>(Wq, wh);
    conv_h<<<(EMB * EMB) / 1024, 256>>>(Wk, wh + EMB * EMB);
    conv_h<<<(EMB * EMB) / 1024, 256>>>(Wv, wh + 2 * EMB * EMB);
    conv_h<<<(EMB * EMB) / 1024, 256>>>(Wo, wh + 3 * EMB * EMB);

    dim3 ggrid(EMB / 128, M_TOK / 128);   // (8, 32)
    gemm_h<<<ggrid, 256, GSMEM>>>(xh, wh,                 q,    nullptr, 1);
    gemm_h<<<ggrid, 256, GSMEM>>>(xh, wh + EMB * EMB,     k,    nullptr, 1);
    gemm_h<<<ggrid, 256, GSMEM>>>(xh, wh + 2 * EMB * EMB, nullptr, vh,   2);

    rope_h<<<(BATCH * NH * S_LEN * 32) / 256, 256>>>(q, k, qh, kh);

    flash_h<<<dim3(S_LEN / 128, BATCH * NH), 256, FSMEM>>>(qh, kh, vh, atth);

    gemm_h<<<ggrid, 256, GSMEM>>>(atth, wh + 3 * EMB * EMB, out, nullptr, 0);
}

// round 8
// speedup vs baseline: 7.8771x; 1.0342x over previous
#include <cuda_runtime.h>
#include <cuda_fp16.h>
#include <math.h>
#include <stdint.h>

#define S_LEN 2048
#define EMB   1024
#define NH    16
#define HD    64
#define BATCH 2
#define M_TOK (BATCH * S_LEN)   // 4096

// ---------------- scratch (device globals) ---------------------------------
__device__ __half g_qh[BATCH * NH * S_LEN * HD];  // half [B,H,S,D]
__device__ __half g_kh[BATCH * NH * S_LEN * HD];
__device__ __half g_vh[BATCH * NH * S_LEN * HD];
__device__ __half g_xh[(size_t)M_TOK * EMB];      // half x [4096,1024]
__device__ __half g_wh[4 * EMB * EMB];            // half Wq|Wk|Wv | Wo
__device__ __half g_atth[(size_t)M_TOK * EMB];    // half attn out [B,S,E]

// ---------------- PTX helpers ----------------------------------------------
__device__ __forceinline__ uint32_t smem_u32(const void* p) {
    uint32_t a;
    asm("{ .reg .u64 t; cvta.to.shared.u64 t, %1; cvt.u32.u64 %0, t; }"
        : "=r"(a) : "l"(p));
    return a;
}
__device__ __forceinline__ void cp16(uint32_t s, const void* g) {
    asm volatile("cp.async.cg.shared.global [%0], [%1], 16;" :: "r"(s), "l"(g) : "memory");
}
__device__ __forceinline__ void cp_commit() {
    asm volatile("cp.async.commit_group;" ::: "memory");
}
#define CP_WAIT(n) asm volatile("cp.async.wait_group %0;" :: "n"(n) : "memory")

__device__ __forceinline__ void ldsm4(uint32_t* r, uint32_t addr) {
    asm volatile("ldmatrix.sync.aligned.m8n8.x4.shared.b16 {%0,%1,%2,%3}, [%4];"
                 : "=r"(r[0]), "=r"(r[1]), "=r"(r[2]), "=r"(r[3]) : "r"(addr));
}
__device__ __forceinline__ void ldsm4t(uint32_t* r, uint32_t addr) {
    asm volatile("ldmatrix.sync.aligned.m8n8.x4.trans.shared.b16 {%0,%1,%2,%3}, [%4];"
                 : "=r"(r[0]), "=r"(r[1]), "=r"(r[2]), "=r"(r[3]) : "r"(addr));
}
__device__ __forceinline__ void mma_h(float* c, const uint32_t* a,
                                      uint32_t b0, uint32_t b1) {
    asm volatile(
        "mma.sync.aligned.m16n8k16.row.col.f32.f16.f16.f32 "
        "{%0,%1,%2,%3}, {%4,%5,%6,%7}, {%8,%9}, {%0,%1,%2,%3};"
        : "+f"(c[0]), "+f"(c[1]), "+f"(c[2]), "+f"(c[3])
        : "r"(a[0]), "r"(a[1]), "r"(a[2]), "r"(a[3]), "r"(b0), "r"(b1));
}
__device__ __forceinline__ uint32_t pack2(float a, float b) {
    __half2 h = __floats2half2_rn(a, b);
    return *reinterpret_cast<uint32_t*>(&h);
}

// ---------------------------------------------------------------------------
// Fused fp32->half conversion of x and the 4 weights (one launch).
// float4 index space: [0, 1M) = x, then 256K per weight. 2M units total.
// ---------------------------------------------------------------------------
__global__ __launch_bounds__(256) void conv_all(const float* __restrict__ x,
                                                const float* __restrict__ Wq,
                                                const float* __restrict__ Wk,
                                                const float* __restrict__ Wv,
                                                const float* __restrict__ Wo,
                                                __half* __restrict__ xh,
                                                __half* __restrict__ wh)
{
    int u = blockIdx.x * 256 + threadIdx.x;     // float4 units, 2M total
    const float* src;
    __half* dst;
    int off;
    if (u < (1 << 20)) { src = x; dst = xh; off = u; }
    else {
        int w = (u - (1 << 20)) >> 18;          // 0..3
        off = (u - (1 << 20)) & ((1 << 18) - 1);
        src = (w == 0) ? Wq : (w == 1) ? Wk : (w == 2) ? Wv : Wo;
        dst = wh + (size_t)w * EMB * EMB;
    }
    float4 v = *(const float4*)&src[off * 4];
    uint2 o;
    o.x = pack2(v.x, v.y);
    o.y = pack2(v.z, v.w);
    *(uint2*)&dst[off * 4] = o;
}

// ---------------------------------------------------------------------------
// half mma GEMM v2: warp tile 64x64, 4 warps, CTA tile 128x128.
// C[M=4096, N] = A[4096,1024] @ W[N,1024]^T, fp32 accum.
// mode 0: fp32 row-major [M,1024] (Wo projection -> d_out)
// mode 1: merged QKV (N=3072): half scatter into qh/kh/vh [B,H,S,D]
// ---------------------------------------------------------------------------
#define GSMEM (3 * 32768)

__global__ __launch_bounds__(128, 2) void gemm_h2(const __half* __restrict__ A,
                                                  const __half* __restrict__ W,
                                                  float* __restrict__ Cf,
                                                  __half* __restrict__ Qo,
                                                  __half* __restrict__ Ko,
                                                  __half* __restrict__ Vo,
                                                  int mode)
{
    extern __shared__ char smx[];
    const uint32_t sb = smem_u32(smx);
    const int tid = threadIdx.x, wid = tid >> 5, lane = tid & 31;
    const int bn0 = blockIdx.x * 128, bm0 = blockIdx.y * 128;
    const int wm = (wid & 1) * 64, wn = (wid >> 1) * 64;

    const int g = lane >> 3;
    const int arow = (g & 1) * 8 + (lane & 7);
    const int ac16 = g >> 1;
    const int brow = (g >> 1) * 8 + (lane & 7);
    const int bc16 = g & 1;

    auto load = [&](int ck, int st) {
        uint32_t Ab = sb + st * 32768, Bb = Ab + 16384;
#pragma unroll
        for (int j = 0; j < 8; j++) {
            int idx = tid + j * 128;
            int r = idx >> 3, c16 = idx & 7;
            uint32_t sw = (uint32_t)(r * 128) + (uint32_t)((c16 ^ (r & 7)) << 4);
            cp16(Ab + sw, A + (size_t)(bm0 + r) * 1024 + ck * 64 + c16 * 8);
            cp16(Bb + sw, W + (size_t)(bn0 + r) * 1024 + ck * 64 + c16 * 8);
        }
        cp_commit();
    };
    load(0, 0); load(1, 1); load(2, 2);

    float acc[4][8][4];
#pragma unroll
    for (int mb = 0; mb < 4; mb++)
#pragma unroll
        for (int nf = 0; nf < 8; nf++)
#pragma unroll
            for (int i = 0; i < 4; i++) acc[mb][nf][i] = 0.0f;

    for (int c = 0; c < 16; c++) {
        int st = c % 3;
        if (c < 14)       { CP_WAIT(2); }
        else if (c == 14) { CP_WAIT(1); }
        else              { CP_WAIT(0); }
        __syncthreads();

        uint32_t Ab = sb + st * 32768, Bb = Ab + 16384;
#pragma unroll
        for (int ks = 0; ks < 4; ks++) {
            uint32_t af[4][4];
#pragma unroll
            for (int mb = 0; mb < 4; mb++) {
                int row = wm + mb * 16 + arow;
                ldsm4(af[mb], Ab + row * 128 + (((2 * ks + ac16) ^ (row & 7)) << 4));
            }
#pragma unroll
            for (int pn = 0; pn < 4; pn++) {
                uint32_t bf[4];
                int rowb = wn + pn * 16 + brow;
                ldsm4(bf, Bb + rowb * 128 + (((2 * ks + bc16) ^ (rowb & 7)) << 4));
#pragma unroll
                for (int mb = 0; mb < 4; mb++) {
                    mma_h(acc[mb][2 * pn],     af[mb], bf[0], bf[1]);
                    mma_h(acc[mb][2 * pn + 1], af[mb], bf[2], bf[3]);
                }
            }
        }
        __syncthreads();
        if (c + 3 < 16) load(c + 3, st);
    }

    // ---- epilogue ----------------------------------------------------------
#pragma unroll
    for (int mb = 0; mb < 4; mb++) {
        int m0 = bm0 + wm + mb * 16 + (lane >> 2);
#pragma unroll
        for (int nf = 0; nf < 8; nf++) {
            int n0 = bn0 + wn + nf * 8 + 2 * (lane & 3);
            if (mode == 0) {
                *(float2*)&Cf[(size_t)m0 * 1024 + n0] =
                    make_float2(acc[mb][nf][0], acc[mb][nf][1]);
                *(float2*)&Cf[(size_t)(m0 + 8) * 1024 + n0] =
                    make_float2(acc[mb][nf][2], acc[mb][nf][3]);
            } else {
                int proj = n0 >> 10;
                int within = n0 & 1023;
                int h = within >> 6, d = within & 63;
                __half* dstp = (proj == 0) ? Qo : (proj == 1) ? Ko : Vo;
#pragma unroll
                for (int rr = 0; rr < 2; rr++) {
                    int m = m0 + 8 * rr;
                    int b = m >> 11, s2 = m & 2047;
                    size_t dst = ((((size_t)(b * NH + h) * S_LEN + s2)) << 6) + d;
                    *(uint32_t*)&dstp[dst] =
                        pack2(acc[mb][nf][rr * 2], acc[mb][nf][rr * 2 + 1]);
                }
            }
        }
    }
}

// ---------------------------------------------------------------------------
// RoPE in-place on half q,k ([B,H,S,D]); pair (d, d+32); q scaled by 1/8.
// ---------------------------------------------------------------------------
__global__ __launch_bounds__(256) void rope_h(__half* __restrict__ qh,
                                              __half* __restrict__ kh)
{
    int t = blockIdx.x * blockDim.x + threadIdx.x;
    int i  = t & 31;
    int s  = (t >> 5) & (S_LEN - 1);
    int bh = t >> 16;
    float inv_freq = powf(10000.0f, -(float)i * (1.0f / 32.0f));
    float theta = (float)s * inv_freq;
    float sn, cs;
    sincosf(theta, &sn, &cs);
    size_t base = ((size_t)bh * S_LEN + s) * HD;
    float q1 = __half2float(qh[base + i]), q2 = __half2float(qh[base + i + 32]);
    qh[base + i]      = __float2half((q1 * cs - q2 * sn) * 0.125f);
    qh[base + i + 32] = __float2half((q2 * cs + q1 * sn) * 0.125f);
    float k1 = __half2float(kh[base + i]), k2 = __half2float(kh[base + i + 32]);
    kh[base + i]      = __float2half(k1 * cs - k2 * sn);
    kh[base + i + 32] = __float2half(k2 * cs + k1 * sn);
}

// ---------------------------------------------------------------------------
// Causal flash attention, fp16 mma, P in registers (C-frag -> A-frag).
// CTA: 128 q rows (8 warps x 16), KV tiles 64, double-buffered cp.async.
// smem: Q 16KB | K 2x8KB | V 2x8KB = 48KB
// ---------------------------------------------------------------------------
#define FSMEM (16384 + 16384 + 16384)

__global__ __launch_bounds__(256, 2) void flash_h(const __half* __restrict__ Q,
                                                  const __half* __restrict__ K,
                                                  const __half* __restrict__ V,
                                                  __half* __restrict__ O)
{
    extern __shared__ char smx[];
    const uint32_t sb = smem_u32(smx);
    const int tid = threadIdx.x, wid = tid >> 5, lane = tid & 31;
    const int qt = gridDim.x - 1 - blockIdx.x;   // largest tiles first
    const int bh = blockIdx.y;

    const uint32_t Qs  = sb;
    const uint32_t Ks0 = sb + 16384;
    const uint32_t Vs0 = sb + 32768;

    const __half* Qg = Q + ((size_t)bh * S_LEN + qt * 128) * HD;
    const __half* Kg = K + (size_t)bh * S_LEN * HD;
    const __half* Vg = V + (size_t)bh * S_LEN * HD;

    const int g = lane >> 3;
    const int arow = (g & 1) * 8 + (lane & 7);
    const int ac16 = g >> 1;
    const int brow = (g >> 1) * 8 + (lane & 7);
    const int bc16 = g & 1;

    auto loadKV = [&](int kt, int st) {
#pragma unroll
        for (int j = 0; j < 2; j++) {
            int idx = tid + j * 256;
            int r = idx >> 3, c16 = idx & 7;
            uint32_t sw = (uint32_t)(r * 128) + (uint32_t)((c16 ^ (r & 7)) << 4);
            cp16(Ks0 + st * 8192 + sw, Kg + (size_t)(kt * 64 + r) * HD + c16 * 8);
            cp16(Vs0 + st * 8192 + sw, Vg + (size_t)(kt * 64 + r) * HD + c16 * 8);
        }
    };

#pragma unroll
    for (int j = 0; j < 4; j++) {
        int idx = tid + j * 256;
        int r = idx >> 3, c16 = idx & 7;
        uint32_t sw = (uint32_t)(r * 128) + (uint32_t)((c16 ^ (r & 7)) << 4);
        cp16(Qs + sw, Qg + (size_t)r * HD + c16 * 8);
    }
    loadKV(0, 0);
    cp_commit();

    const int ktmax = 2 * qt + 1;
    uint32_t qf[4][4];
    float accO[8][4];
#pragma unroll
    for (int d = 0; d < 8; d++)
#pragma unroll
        for (int i = 0; i < 4; i++) accO[d][i] = 0.0f;
    float m_r[2] = {-1e30f, -1e30f};
    float l_r[2] = {0.0f, 0.0f};

    for (int kt = 0; kt <= ktmax; kt++) {
        const int st = kt & 1;
        if (kt < ktmax) { loadKV(kt + 1, st ^ 1); cp_commit(); CP_WAIT(1); }
        else            { CP_WAIT(0); }
        __syncthreads();

        if (kt == 0) {
#pragma unroll
            for (int ks = 0; ks < 4; ks++) {
                int row = wid * 16 + arow;
                ldsm4(qf[ks], Qs + row * 128 + (((2 * ks + ac16) ^ (row & 7)) << 4));
            }
        }

        const uint32_t Kst = Ks0 + st * 8192;
        const uint32_t Vst = Vs0 + st * 8192;

        float S[8][4];
#pragma unroll
        for (int n = 0; n < 8; n++)
#pragma unroll
            for (int i = 0; i < 4; i++) S[n][i] = 0.0f;

#pragma unroll
        for (int ks = 0; ks < 4; ks++) {
#pragma unroll
            for (int pn = 0; pn < 4; pn++) {
                uint32_t bf[4];
                int rowb = pn * 16 + brow;
                ldsm4(bf, Kst + rowb * 128 + (((2 * ks + bc16) ^ (rowb & 7)) << 4));
                mma_h(S[2 * pn],     qf[ks], bf[0], bf[1]);
                mma_h(S[2 * pn + 1], qf[ks], bf[2], bf[3]);
            }
        }

        if (kt >= 2 * qt) {
            int rbase = qt * 128 + wid * 16 + (lane >> 2);
#pragma unroll
            for (int nf = 0; nf < 8; nf++) {
                int cc = kt * 64 + nf * 8 + 2 * (lane & 3);
                if (cc     > rbase)     S[nf][0] = -1e30f;
                if (cc + 1 > rbase)     S[nf][1] = -1e30f;
                if (cc     > rbase + 8) S[nf][2] = -1e30f;
                if (cc + 1 > rbase + 8) S[nf][3] = -1e30f;
            }
        }

#pragma unroll
        for (int rh = 0; rh < 2; rh++) {
            float mx = -1e30f;
#pragma unroll
            for (int nf = 0; nf < 8; nf++)
                mx = fmaxf(mx, fmaxf(S[nf][rh * 2], S[nf][rh * 2 + 1]));
            mx = fmaxf(mx, __shfl_xor_sync(0xffffffffu, mx, 1));
            mx = fmaxf(mx, __shfl_xor_sync(0xffffffffu, mx, 2));
            float mn = fmaxf(m_r[rh], mx);
            float alpha = __expf(m_r[rh] - mn);
            float sum = 0.0f;
#pragma unroll
            for (int nf = 0; nf < 8; nf++) {
                float p0 = __expf(S[nf][rh * 2]     - mn);
                float p1 = __expf(S[nf][rh * 2 + 1] - mn);
                S[nf][rh * 2] = p0; S[nf][rh * 2 + 1] = p1;
                sum += p0 + p1;
            }
            sum += __shfl_xor_sync(0xffffffffu, sum, 1);
            sum += __shfl_xor_sync(0xffffffffu, sum, 2);
            l_r[rh] = l_r[rh] * alpha + sum;
            m_r[rh] = mn;
#pragma unroll
            for (int df = 0; df < 8; df++) {
                accO[df][rh * 2]     *= alpha;
                accO[df][rh * 2 + 1] *= alpha;
            }
        }

#pragma unroll
        for (int j = 0; j < 4; j++) {
            uint32_t pa[4];
            pa[0] = pack2(S[2 * j][0],     S[2 * j][1]);
            pa[1] = pack2(S[2 * j][2],     S[2 * j][3]);
            pa[2] = pack2(S[2 * j + 1][0], S[2 * j + 1][1]);
            pa[3] = pack2(S[2 * j + 1][2], S[2 * j + 1][3]);
#pragma unroll
            for (int pn = 0; pn < 4; pn++) {
                uint32_t bv[4];
                int rowv = j * 16 + arow;
                ldsm4t(bv, Vst + rowv * 128 + (((2 * pn + ac16) ^ (rowv & 7)) << 4));
                mma_h(accO[2 * pn],     pa, bv[0], bv[1]);
                mma_h(accO[2 * pn + 1], pa, bv[2], bv[3]);
            }
        }
        __syncthreads();
    }

    float inv0 = 1.0f / l_r[0], inv1 = 1.0f / l_r[1];
    int b = bh >> 4, h = bh & 15;
    int r0 = qt * 128 + wid * 16 + (lane >> 2);
#pragma unroll
    for (int df = 0; df < 8; df++) {
        int d = df * 8 + 2 * (lane & 3);
        size_t a0 = ((size_t)(b * S_LEN + r0)) * EMB + h * 64 + d;
        *(uint32_t*)&O[a0] = pack2(accO[df][0] * inv0, accO[df][1] * inv0);
        *(uint32_t*)&O[a0 + (size_t)8 * EMB] =
            pack2(accO[df][2] * inv1, accO[df][3] * inv1);
    }
}

// ---------------------------------------------------------------------------
extern "C" void kernel_launch(void* const* d_in, const int* in_sizes, int n_in,
                              void* d_out, int out_size)
{
    const float* x  = (const float*)d_in[0];
    const float* Wq = (const float*)d_in[1];
    const float* Wk = (const float*)d_in[2];
    const float* Wv = (const float*)d_in[3];
    const float* Wo = (const float*)d_in[4];
    float* out = (float*)d_out;

    __half *qh, *kh, *vh, *xh, *wh, *atth;
    cudaGetSymbolAddress((void**)&qh,   g_qh);
    cudaGetSymbolAddress((void**)&kh,   g_kh);
    cudaGetSymbolAddress((void**)&vh,   g_vh);
    cudaGetSymbolAddress((void**)&xh,   g_xh);
    cudaGetSymbolAddress((void**)&wh,   g_wh);
    cudaGetSymbolAddress((void**)&atth, g_atth);

    cudaFuncSetAttribute(gemm_h2, cudaFuncAttributeMaxDynamicSharedMemorySize, GSMEM);
    cudaFuncSetAttribute(flash_h, cudaFuncAttributeMaxDynamicSharedMemorySize, FSMEM);

    // one fused conversion pass: x + all four weights (2M float4 units)
    conv_all<<<8192, 256>>>(x, Wq, Wk, Wv, Wo, xh, wh);

    // merged QKV projection: N = 3072
    gemm_h2<<<dim3(24, 32), 128, GSMEM>>>(xh, wh, nullptr, qh, kh, vh, 1);

    rope_h<<<(BATCH * NH * S_LEN * 32) / 256, 256>>>(qh, kh);

    flash_h<<<dim3(S_LEN / 128, BATCH * NH), 256, FSMEM>>>(qh, kh, vh, atth);

    // output projection
    gemm_h2<<<dim3(8, 32), 128, GSMEM>>>(atth, wh + (size_t)3 * EMB * EMB,
                                         out, nullptr, nullptr, nullptr, 0);
}

// round 9
// speedup vs baseline: 8.6971x; 1.1041x over previous
#include <cuda_runtime.h>
#include <cuda_fp16.h>
#include <math.h>
#include <stdint.h>

#define S_LEN 2048
#define EMB   1024
#define NH    16
#define HD    64
#define BATCH 2
#define M_TOK (BATCH * S_LEN)   // 4096

// ---------------- scratch (device globals) ---------------------------------
__device__ __half g_qh[BATCH * NH * S_LEN * HD];  // half [B,H,S,D]
__device__ __half g_kh[BATCH * NH * S_LEN * HD];
__device__ __half g_vh[BATCH * NH * S_LEN * HD];
__device__ __half g_xh[(size_t)M_TOK * EMB];      // half x [4096,1024]
__device__ __half g_wh[4 * EMB * EMB];            // half Wq|Wk|Wv | Wo
__device__ __half g_atth[(size_t)M_TOK * EMB];    // half attn out [B,S,E]

// ---------------- PTX helpers ----------------------------------------------
__device__ __forceinline__ uint32_t smem_u32(const void* p) {
    uint32_t a;
    asm("{ .reg .u64 t; cvta.to.shared.u64 t, %1; cvt.u32.u64 %0, t; }"
        : "=r"(a) : "l"(p));
    return a;
}
__device__ __forceinline__ void cp16(uint32_t s, const void* g) {
    asm volatile("cp.async.cg.shared.global [%0], [%1], 16;" :: "r"(s), "l"(g) : "memory");
}
__device__ __forceinline__ void cp_commit() {
    asm volatile("cp.async.commit_group;" ::: "memory");
}
#define CP_WAIT(n) asm volatile("cp.async.wait_group %0;" :: "n"(n) : "memory")

__device__ __forceinline__ void ldsm4(uint32_t* r, uint32_t addr) {
    asm volatile("ldmatrix.sync.aligned.m8n8.x4.shared.b16 {%0,%1,%2,%3}, [%4];"
                 : "=r"(r[0]), "=r"(r[1]), "=r"(r[2]), "=r"(r[3]) : "r"(addr));
}
__device__ __forceinline__ void ldsm4t(uint32_t* r, uint32_t addr) {
    asm volatile("ldmatrix.sync.aligned.m8n8.x4.trans.shared.b16 {%0,%1,%2,%3}, [%4];"
                 : "=r"(r[0]), "=r"(r[1]), "=r"(r[2]), "=r"(r[3]) : "r"(addr));
}
__device__ __forceinline__ void mma_h(float* c, const uint32_t* a,
                                      uint32_t b0, uint32_t b1) {
    asm volatile(
        "mma.sync.aligned.m16n8k16.row.col.f32.f16.f16.f32 "
        "{%0,%1,%2,%3}, {%4,%5,%6,%7}, {%8,%9}, {%0,%1,%2,%3};"
        : "+f"(c[0]), "+f"(c[1]), "+f"(c[2]), "+f"(c[3])
        : "r"(a[0]), "r"(a[1]), "r"(a[2]), "r"(a[3]), "r"(b0), "r"(b1));
}
__device__ __forceinline__ uint32_t pack2(float a, float b) {
    __half2 h = __floats2half2_rn(a, b);
    return *reinterpret_cast<uint32_t*>(&h);
}
__device__ __forceinline__ float ex2(float x) {
    float y;
    asm("ex2.approx.ftz.f32 %0, %1;" : "=f"(y) : "f"(x));
    return y;
}

// ---------------------------------------------------------------------------
// Fused fp32->half conversion of x and the 4 weights (one launch).
// float4 index space: [0, 1M) = x, then 256K per weight. 2M units total.
// ---------------------------------------------------------------------------
__global__ __launch_bounds__(256) void conv_all(const float* __restrict__ x,
                                                const float* __restrict__ Wq,
                                                const float* __restrict__ Wk,
                                                const float* __restrict__ Wv,
                                                const float* __restrict__ Wo,
                                                __half* __restrict__ xh,
                                                __half* __restrict__ wh)
{
    int u = blockIdx.x * 256 + threadIdx.x;     // float4 units, 2M total
    const float* src;
    __half* dst;
    int off;
    if (u < (1 << 20)) { src = x; dst = xh; off = u; }
    else {
        int w = (u - (1 << 20)) >> 18;          // 0..3
        off = (u - (1 << 20)) & ((1 << 18) - 1);
        src = (w == 0) ? Wq : (w == 1) ? Wk : (w == 2) ? Wv : Wo;
        dst = wh + (size_t)w * EMB * EMB;
    }
    float4 v = *(const float4*)&src[off * 4];
    uint2 o;
    o.x = pack2(v.x, v.y);
    o.y = pack2(v.z, v.w);
    *(uint2*)&dst[off * 4] = o;
}

// ---------------------------------------------------------------------------
// half mma GEMM v2: warp tile 64x64, 4 warps, CTA tile 128x128. (unchanged)
// ---------------------------------------------------------------------------
#define GSMEM (3 * 32768)

__global__ __launch_bounds__(128, 2) void gemm_h2(const __half* __restrict__ A,
                                                  const __half* __restrict__ W,
                                                  float* __restrict__ Cf,
                                                  __half* __restrict__ Qo,
                                                  __half* __restrict__ Ko,
                                                  __half* __restrict__ Vo,
                                                  int mode)
{
    extern __shared__ char smx[];
    const uint32_t sb = smem_u32(smx);
    const int tid = threadIdx.x, wid = tid >> 5, lane = tid & 31;
    const int bn0 = blockIdx.x * 128, bm0 = blockIdx.y * 128;
    const int wm = (wid & 1) * 64, wn = (wid >> 1) * 64;

    const int g = lane >> 3;
    const int arow = (g & 1) * 8 + (lane & 7);
    const int ac16 = g >> 1;
    const int brow = (g >> 1) * 8 + (lane & 7);
    const int bc16 = g & 1;

    auto load = [&](int ck, int st) {
        uint32_t Ab = sb + st * 32768, Bb = Ab + 16384;
#pragma unroll
        for (int j = 0; j < 8; j++) {
            int idx = tid + j * 128;
            int r = idx >> 3, c16 = idx & 7;
            uint32_t sw = (uint32_t)(r * 128) + (uint32_t)((c16 ^ (r & 7)) << 4);
            cp16(Ab + sw, A + (size_t)(bm0 + r) * 1024 + ck * 64 + c16 * 8);
            cp16(Bb + sw, W + (size_t)(bn0 + r) * 1024 + ck * 64 + c16 * 8);
        }
        cp_commit();
    };
    load(0, 0); load(1, 1); load(2, 2);

    float acc[4][8][4];
#pragma unroll
    for (int mb = 0; mb < 4; mb++)
#pragma unroll
        for (int nf = 0; nf < 8; nf++)
#pragma unroll
            for (int i = 0; i < 4; i++) acc[mb][nf][i] = 0.0f;

    for (int c = 0; c < 16; c++) {
        int st = c % 3;
        if (c < 14)       { CP_WAIT(2); }
        else if (c == 14) { CP_WAIT(1); }
        else              { CP_WAIT(0); }
        __syncthreads();

        uint32_t Ab = sb + st * 32768, Bb = Ab + 16384;
#pragma unroll
        for (int ks = 0; ks < 4; ks++) {
            uint32_t af[4][4];
#pragma unroll
            for (int mb = 0; mb < 4; mb++) {
                int row = wm + mb * 16 + arow;
                ldsm4(af[mb], Ab + row * 128 + (((2 * ks + ac16) ^ (row & 7)) << 4));
            }
#pragma unroll
            for (int pn = 0; pn < 4; pn++) {
                uint32_t bf[4];
                int rowb = wn + pn * 16 + brow;
                ldsm4(bf, Bb + rowb * 128 + (((2 * ks + bc16) ^ (rowb & 7)) << 4));
#pragma unroll
                for (int mb = 0; mb < 4; mb++) {
                    mma_h(acc[mb][2 * pn],     af[mb], bf[0], bf[1]);
                    mma_h(acc[mb][2 * pn + 1], af[mb], bf[2], bf[3]);
                }
            }
        }
        __syncthreads();
        if (c + 3 < 16) load(c + 3, st);
    }

#pragma unroll
    for (int mb = 0; mb < 4; mb++) {
        int m0 = bm0 + wm + mb * 16 + (lane >> 2);
#pragma unroll
        for (int nf = 0; nf < 8; nf++) {
            int n0 = bn0 + wn + nf * 8 + 2 * (lane & 3);
            if (mode == 0) {
                *(float2*)&Cf[(size_t)m0 * 1024 + n0] =
                    make_float2(acc[mb][nf][0], acc[mb][nf][1]);
                *(float2*)&Cf[(size_t)(m0 + 8) * 1024 + n0] =
                    make_float2(acc[mb][nf][2], acc[mb][nf][3]);
            } else {
                int proj = n0 >> 10;
                int within = n0 & 1023;
                int h = within >> 6, d = within & 63;
                __half* dstp = (proj == 0) ? Qo : (proj == 1) ? Ko : Vo;
#pragma unroll
                for (int rr = 0; rr < 2; rr++) {
                    int m = m0 + 8 * rr;
                    int b = m >> 11, s2 = m & 2047;
                    size_t dst = ((((size_t)(b * NH + h) * S_LEN + s2)) << 6) + d;
                    *(uint32_t*)&dstp[dst] =
                        pack2(acc[mb][nf][rr * 2], acc[mb][nf][rr * 2 + 1]);
                }
            }
        }
    }
}

// ---------------------------------------------------------------------------
// RoPE in-place; q additionally scaled by 0.125 * log2(e) (exp2 softmax).
// ---------------------------------------------------------------------------
#define QSCALE 0.180336879f   // 0.125 * log2(e)

__global__ __launch_bounds__(256) void rope_h(__half* __restrict__ qh,
                                              __half* __restrict__ kh)
{
    int t = blockIdx.x * blockDim.x + threadIdx.x;
    int i  = t & 31;
    int s  = (t >> 5) & (S_LEN - 1);
    int bh = t >> 16;
    float inv_freq = powf(10000.0f, -(float)i * (1.0f / 32.0f));
    float theta = (float)s * inv_freq;
    float sn, cs;
    sincosf(theta, &sn, &cs);
    size_t base = ((size_t)bh * S_LEN + s) * HD;
    float q1 = __half2float(qh[base + i]), q2 = __half2float(qh[base + i + 32]);
    qh[base + i]      = __float2half((q1 * cs - q2 * sn) * QSCALE);
    qh[base + i + 32] = __float2half((q2 * cs + q1 * sn) * QSCALE);
    float k1 = __half2float(kh[base + i]), k2 = __half2float(kh[base + i + 32]);
    kh[base + i]      = __float2half(k1 * cs - k2 * sn);
    kh[base + i + 32] = __float2half(k2 * cs + k1 * sn);
}

// ---------------------------------------------------------------------------
// Causal flash attention v3: 4 warps / 64 q-rows per CTA, exp2 softmax,
// single masked diagonal tile. KV tiles 64, double-buffered cp.async.
// smem: Q 8KB | K 2x8KB | V 2x8KB = 40KB  -> 4 CTAs/SM (reg-capped 16 warps)
// ---------------------------------------------------------------------------
#define FSMEM (8192 + 16384 + 16384)

__global__ __launch_bounds__(128, 4) void flash_h(const __half* __restrict__ Q,
                                                  const __half* __restrict__ K,
                                                  const __half* __restrict__ V,
                                                  __half* __restrict__ O)
{
    extern __shared__ char smx[];
    const uint32_t sb = smem_u32(smx);
    const int tid = threadIdx.x, wid = tid >> 5, lane = tid & 31;
    const int qt = gridDim.x - 1 - blockIdx.x;   // largest tiles first
    const int bh = blockIdx.y;

    const uint32_t Qs  = sb;
    const uint32_t Ks0 = sb + 8192;
    const uint32_t Vs0 = sb + 24576;

    const __half* Qg = Q + ((size_t)bh * S_LEN + qt * 64) * HD;
    const __half* Kg = K + (size_t)bh * S_LEN * HD;
    const __half* Vg = V + (size_t)bh * S_LEN * HD;

    const int g = lane >> 3;
    const int arow = (g & 1) * 8 + (lane & 7);
    const int ac16 = g >> 1;
    const int brow = (g >> 1) * 8 + (lane & 7);
    const int bc16 = g & 1;

    auto loadKV = [&](int kt, int st) {
#pragma unroll
        for (int j = 0; j < 4; j++) {
            int idx = tid + j * 128;            // 0..511
            int r = idx >> 3, c16 = idx & 7;
            uint32_t sw = (uint32_t)(r * 128) + (uint32_t)((c16 ^ (r & 7)) << 4);
            cp16(Ks0 + st * 8192 + sw, Kg + (size_t)(kt * 64 + r) * HD + c16 * 8);
            cp16(Vs0 + st * 8192 + sw, Vg + (size_t)(kt * 64 + r) * HD + c16 * 8);
        }
    };

    // group 0: Q tile (64 rows) + KV tile 0
#pragma unroll
    for (int j = 0; j < 4; j++) {
        int idx = tid + j * 128;
        int r = idx >> 3, c16 = idx & 7;
        uint32_t sw = (uint32_t)(r * 128) + (uint32_t)((c16 ^ (r & 7)) << 4);
        cp16(Qs + sw, Qg + (size_t)r * HD + c16 * 8);
    }
    loadKV(0, 0);
    cp_commit();

    uint32_t qf[4][4];
    float accO[8][4];
#pragma unroll
    for (int d = 0; d < 8; d++)
#pragma unroll
        for (int i = 0; i < 4; i++) accO[d][i] = 0.0f;
    float m_r[2] = {-1e30f, -1e30f};
    float l_r[2] = {0.0f, 0.0f};

    for (int kt = 0; kt <= qt; kt++) {
        const int st = kt & 1;
        if (kt < qt) { loadKV(kt + 1, st ^ 1); cp_commit(); CP_WAIT(1); }
        else         { CP_WAIT(0); }
        __syncthreads();

        if (kt == 0) {
#pragma unroll
            for (int ks = 0; ks < 4; ks++) {
                int row = wid * 16 + arow;
                ldsm4(qf[ks], Qs + row * 128 + (((2 * ks + ac16) ^ (row & 7)) << 4));
            }
        }

        const uint32_t Kst = Ks0 + st * 8192;
        const uint32_t Vst = Vs0 + st * 8192;

        // ---- S = Q @ K^T (log2-scaled) -----------------------------------
        float S[8][4];
#pragma unroll
        for (int n = 0; n < 8; n++)
#pragma unroll
            for (int i = 0; i < 4; i++) S[n][i] = 0.0f;

#pragma unroll
        for (int ks = 0; ks < 4; ks++) {
#pragma unroll
            for (int pn = 0; pn < 4; pn++) {
                uint32_t bf[4];
                int rowb = pn * 16 + brow;
                ldsm4(bf, Kst + rowb * 128 + (((2 * ks + bc16) ^ (rowb & 7)) << 4));
                mma_h(S[2 * pn],     qf[ks], bf[0], bf[1]);
                mma_h(S[2 * pn + 1], qf[ks], bf[2], bf[3]);
            }
        }

        // ---- causal mask (single diagonal tile) --------------------------
        if (kt == qt) {
            int rbase = wid * 16 + (lane >> 2);      // both tiles share kt*64 base
#pragma unroll
            for (int nf = 0; nf < 8; nf++) {
                int cc = nf * 8 + 2 * (lane & 3);
                if (cc     > rbase)     S[nf][0] = -1e30f;
                if (cc + 1 > rbase)     S[nf][1] = -1e30f;
                if (cc     > rbase + 8) S[nf][2] = -1e30f;
                if (cc + 1 > rbase + 8) S[nf][3] = -1e30f;
            }
        }

        // ---- online softmax (base-2) -------------------------------------
#pragma unroll
        for (int rh = 0; rh < 2; rh++) {
            float mx = -1e30f;
#pragma unroll
            for (int nf = 0; nf < 8; nf++)
                mx = fmaxf(mx, fmaxf(S[nf][rh * 2], S[nf][rh * 2 + 1]));
            mx = fmaxf(mx, __shfl_xor_sync(0xffffffffu, mx, 1));
            mx = fmaxf(mx, __shfl_xor_sync(0xffffffffu, mx, 2));
            float mn = fmaxf(m_r[rh], mx);
            float alpha = ex2(m_r[rh] - mn);
            float sum = 0.0f;
#pragma unroll
            for (int nf = 0; nf < 8; nf++) {
                float p0 = ex2(S[nf][rh * 2]     - mn);
                float p1 = ex2(S[nf][rh * 2 + 1] - mn);
                S[nf][rh * 2] = p0; S[nf][rh * 2 + 1] = p1;
                sum += p0 + p1;
            }
            sum += __shfl_xor_sync(0xffffffffu, sum, 1);
            sum += __shfl_xor_sync(0xffffffffu, sum, 2);
            l_r[rh] = l_r[rh] * alpha + sum;
            m_r[rh] = mn;
#pragma unroll
            for (int df = 0; df < 8; df++) {
                accO[df][rh * 2]     *= alpha;
                accO[df][rh * 2 + 1] *= alpha;
            }
        }

        // ---- O += P @ V (P from registers) -------------------------------
#pragma unroll
        for (int j = 0; j < 4; j++) {
            uint32_t pa[4];
            pa[0] = pack2(S[2 * j][0],     S[2 * j][1]);
            pa[1] = pack2(S[2 * j][2],     S[2 * j][3]);
            pa[2] = pack2(S[2 * j + 1][0], S[2 * j + 1][1]);
            pa[3] = pack2(S[2 * j + 1][2], S[2 * j + 1][3]);
#pragma unroll
            for (int pn = 0; pn < 4; pn++) {
                uint32_t bv[4];
                int rowv = j * 16 + arow;
                ldsm4t(bv, Vst + rowv * 128 + (((2 * pn + ac16) ^ (rowv & 7)) << 4));
                mma_h(accO[2 * pn],     pa, bv[0], bv[1]);
                mma_h(accO[2 * pn + 1], pa, bv[2], bv[3]);
            }
        }
        __syncthreads();
    }

    // ---- epilogue: half att [B,S,E] --------------------------------------
    float inv0 = 1.0f / l_r[0], inv1 = 1.0f / l_r[1];
    int b = bh >> 4, h = bh & 15;
    int r0 = qt * 64 + wid * 16 + (lane >> 2);
#pragma unroll
    for (int df = 0; df < 8; df++) {
        int d = df * 8 + 2 * (lane & 3);
        size_t a0 = ((size_t)(b * S_LEN + r0)) * EMB + h * 64 + d;
        *(uint32_t*)&O[a0] = pack2(accO[df][0] * inv0, accO[df][1] * inv0);
        *(uint32_t*)&O[a0 + (size_t)8 * EMB] =
            pack2(accO[df][2] * inv1, accO[df][3] * inv1);
    }
}

// ---------------------------------------------------------------------------
extern "C" void kernel_launch(void* const* d_in, const int* in_sizes, int n_in,
                              void* d_out, int out_size)
{
    const float* x  = (const float*)d_in[0];
    const float* Wq = (const float*)d_in[1];
    const float* Wk = (const float*)d_in[2];
    const float* Wv = (const float*)d_in[3];
    const float* Wo = (const float*)d_in[4];
    float* out = (float*)d_out;

    __half *qh, *kh, *vh, *xh, *wh, *atth;
    cudaGetSymbolAddress((void**)&qh,   g_qh);
    cudaGetSymbolAddress((void**)&kh,   g_kh);
    cudaGetSymbolAddress((void**)&vh,   g_vh);
    cudaGetSymbolAddress((void**)&xh,   g_xh);
    cudaGetSymbolAddress((void**)&wh,   g_wh);
    cudaGetSymbolAddress((void**)&atth, g_atth);

    cudaFuncSetAttribute(gemm_h2, cudaFuncAttributeMaxDynamicSharedMemorySize, GSMEM);
    cudaFuncSetAttribute(flash_h, cudaFuncAttributeMaxDynamicSharedMemorySize, FSMEM);

    // one fused conversion pass: x + all four weights (2M float4 units)
    conv_all<<<8192, 256>>>(x, Wq, Wk, Wv, Wo, xh, wh);

    // merged QKV projection: N = 3072
    gemm_h2<<<dim3(24, 32), 128, GSMEM>>>(xh, wh, nullptr, qh, kh, vh, 1);

    rope_h<<<(BATCH * NH * S_LEN * 32) / 256, 256>>>(qh, kh);

    flash_h<<<dim3(S_LEN / 64, BATCH * NH), 128, FSMEM>>>(qh, kh, vh, atth);

    // output projection
    gemm_h2<<<dim3(8, 32), 128, GSMEM>>>(atth, wh + (size_t)3 * EMB * EMB,
                                         out, nullptr, nullptr, nullptr, 0);
}